// round 5
// baseline (speedup 1.0000x reference)
#include <cuda_runtime.h>
#include <cuda_bf16.h>

#define T_STEPS 256
#define BATCH   128
#define DIM_IN  512
#define HID     512
#define NQ      8
#define QDIM    256   // 2^8

// role layout in the fused grid
#define CIRC_BLKS  4
#define XDOT_BLKS  4096                     // 32768 rows / 8 rows per block
#define SCAN_BID   (CIRC_BLKS + XDOT_BLKS)  // 4100
#define BCAST0     (SCAN_BID + 1)           // 4101
#define BCAST_BLKS 16512
#define GRID_BLKS  (BCAST0 + BCAST_BLKS)    // 20613

// ---------------- scratch (no allocations allowed) ----------------
__device__ float4 g_xdot[T_STEPS * BATCH];   // per (t,b): raw dots for f,i,g,o
__device__ float  g_H[T_STEPS * BATCH];      // scalar hidden state per (t,b)
__device__ float  g_Cfin[BATCH];             // final cell scalar per b
// per gate: [0]=wsum  [1]=b0-phi  [2]=alpha/2  [3]=R/2  [4]=alpha  [5]=R
__device__ float  g_par[4][6];
// pipeline flags (reset by init_kernel every launch)
__device__ int    g_xcnt[T_STEPS];   // xdot blocks completed per t (target 16)
__device__ int    g_parflag;         // circuits completed (target 4)
__device__ int    g_hprog;           // scan progress: H[0..g_hprog) valid; 256 = all + Cfin

__device__ __forceinline__ float2 cmul(float2 a, float2 b) {
    return make_float2(a.x * b.x - a.y * b.y, a.x * b.y + a.y * b.x);
}
__device__ __forceinline__ float2 cadd(float2 a, float2 b) {
    return make_float2(a.x + b.x, a.y + b.y);
}
__device__ __forceinline__ float htanh(float x) {
    float y;
    asm("tanh.approx.f32 %0, %1;" : "=f"(y) : "f"(x));
    return y;
}
__device__ __forceinline__ int vload(const int* p) {
    return *(volatile const int*)p;
}

// ---------------- init: zero the pipeline flags ----------------
__global__ void init_kernel()
{
    int i = threadIdx.x;
    if (i < T_STEPS) g_xcnt[i] = 0;
    if (i == 0) { g_parflag = 0; g_hprog = 0; }
}

// ---------------- circuit: simulate one variational circuit ----------------
// Statevector-simulates columns 0 and 128 of the 2-layer circuit, reduces to
// expval(theta) = alpha + R*cos(theta - phi), plus wsum and b0-phi.
__device__ void circuit_block(int g, const float* __restrict__ P,
                              const float* __restrict__ W, const float* __restrict__ bv)
{
    __shared__ float2 a0[QDIM], a1[QDIM];
    __shared__ float  r0[QDIM], r1[QDIM], r2[QDIM];
    int d = threadIdx.x;

    a0[d] = make_float2(d == 0 ? 1.f : 0.f, 0.f);
    a1[d] = make_float2(d == QDIM / 2 ? 1.f : 0.f, 0.f);

    for (int l = 0; l < 2; l++) {
        for (int w = 0; w < NQ; w++) {
            const float* p = P + (l * NQ + w) * 3;
            float phi = p[0], th = p[1], om = p[2];
            float c, s;  __sincosf(0.5f * th, &s, &c);
            float cap, sap; __sincosf(0.5f * (phi + om), &sap, &cap);
            float cbm, sbm; __sincosf(0.5f * (phi - om), &sbm, &cbm);
            float2 m00 = make_float2(cap * c, -sap * c);     // ep*c
            float2 m01 = make_float2(-cbm * s, -sbm * s);    // -em*s
            float2 m10 = make_float2(cbm * s, -sbm * s);     // conj(em)*s
            float2 m11 = make_float2(cap * c, sap * c);      // conj(ep)*c

            int p7 = 7 - w;
            int mask = 1 << p7;
            int bit = (d >> p7) & 1;
            __syncthreads();
            float2 me0 = a0[d], pa0 = a0[d ^ mask];
            float2 me1 = a1[d], pa1 = a1[d ^ mask];
            __syncthreads();
            float2 n0, n1;
            if (!bit) {
                n0 = cadd(cmul(m00, me0), cmul(m01, pa0));
                n1 = cadd(cmul(m00, me1), cmul(m01, pa1));
            } else {
                n0 = cadd(cmul(m10, pa0), cmul(m11, me0));
                n1 = cadd(cmul(m10, pa1), cmul(m11, me1));
            }
            a0[d] = n0; a1[d] = n1;
        }
        for (int w = 0; w < NQ - 1; w++) {
            int pc = 7 - w, pt = 6 - w;
            __syncthreads();
            int src = ((d >> pc) & 1) ? (d ^ (1 << pt)) : d;
            float2 v0 = a0[src], v1 = a1[src];
            __syncthreads();
            a0[d] = v0; a1[d] = v1;
        }
    }
    __syncthreads();

    float z = (d < QDIM / 2) ? 1.f : -1.f;
    float2 c0 = a0[d], c1 = a1[d];
    r0[d] = z * (c0.x * c0.x + c0.y * c0.y);
    r1[d] = z * (c1.x * c1.x + c1.y * c1.y);
    r2[d] = z * (c0.y * c1.x - c0.x * c1.y);
    __syncthreads();
    for (int off = QDIM / 2; off; off >>= 1) {
        if (d < off) { r0[d] += r0[d + off]; r1[d] += r1[d + off]; r2[d] += r2[d + off]; }
        __syncthreads();
    }
    float S00 = r0[0], S11 = r1[0], S01 = r2[0];
    __syncthreads();

    r0[d] = W[512 + d] + W[512 + QDIM + d];
    __syncthreads();
    for (int off = QDIM / 2; off; off >>= 1) {
        if (d < off) r0[d] += r0[d + off];
        __syncthreads();
    }
    if (d == 0) {
        float alpha = 0.5f * (S00 + S11);
        float beta  = 0.5f * (S00 - S11);
        float gamma = -S01;
        float R   = sqrtf(beta * beta + gamma * gamma);
        float phi = atan2f(gamma, beta);
        g_par[g][0] = r0[0];          // wsum
        g_par[g][1] = bv[0] - phi;    // theta offset (added in scan)
        g_par[g][2] = 0.5f * alpha;
        g_par[g][3] = 0.5f * R;
        g_par[g][4] = alpha;
        g_par[g][5] = R;
        __threadfence();                       // release g_par
        atomicAdd(&g_parflag, 1);
    }
}

// ---------------- fused pipeline kernel ----------------
__global__ void __launch_bounds__(256) pipe_kernel(
    float4* __restrict__ out,
    const float* __restrict__ X,
    const float* __restrict__ Wf, const float* __restrict__ Wi,
    const float* __restrict__ Wg, const float* __restrict__ Wo,
    const float* __restrict__ bfv, const float* __restrict__ biv,
    const float* __restrict__ bgv, const float* __restrict__ bov,
    const float* __restrict__ Pf, const float* __restrict__ Pi,
    const float* __restrict__ Pg, const float* __restrict__ Po)
{
    int bid = blockIdx.x;
    int tid = threadIdx.x;

    // ================= role: circuit =================
    if (bid < CIRC_BLKS) {
        int g = bid;
        const float* P  = (g == 0) ? Pf : (g == 1) ? Pi : (g == 2) ? Pg : Po;
        const float* W  = (g == 0) ? Wf : (g == 1) ? Wi : (g == 2) ? Wg : Wo;
        const float* bv = (g == 0) ? bfv : (g == 1) ? biv : (g == 2) ? bgv : bov;
        circuit_block(g, P, W, bv);
        return;
    }

    // ================= role: xdot producer =================
    if (bid < SCAN_BID) {
        int j    = bid - CIRC_BLKS;          // 0..4095
        int row  = j * 8 + (tid >> 5);       // 8 rows per block, all in t = j>>4
        int lane = tid & 31;

        const float4* xr = (const float4*)(X + (size_t)row * DIM_IN);
        const float4* wf = (const float4*)Wf;
        const float4* wi = (const float4*)Wi;
        const float4* wg = (const float4*)Wg;
        const float4* wo = (const float4*)Wo;

        float sf = 0.f, si = 0.f, sg = 0.f, so = 0.f;
#pragma unroll
        for (int jj = 0; jj < 4; jj++) {
            int k = lane + 32 * jj;
            float4 xv = xr[k];
            float4 a = __ldg(wf + k); sf += xv.x * a.x + xv.y * a.y + xv.z * a.z + xv.w * a.w;
            float4 b = __ldg(wi + k); si += xv.x * b.x + xv.y * b.y + xv.z * b.z + xv.w * b.w;
            float4 c = __ldg(wg + k); sg += xv.x * c.x + xv.y * c.y + xv.z * c.z + xv.w * c.w;
            float4 e = __ldg(wo + k); so += xv.x * e.x + xv.y * e.y + xv.z * e.z + xv.w * e.w;
        }
#pragma unroll
        for (int o = 16; o; o >>= 1) {
            sf += __shfl_xor_sync(0xffffffffu, sf, o);
            si += __shfl_xor_sync(0xffffffffu, si, o);
            sg += __shfl_xor_sync(0xffffffffu, sg, o);
            so += __shfl_xor_sync(0xffffffffu, so, o);
        }
        if (lane == 0) {
            g_xdot[row] = make_float4(sf, si, sg, so);
            __threadfence();                 // release this row
        }
        __syncthreads();
        if (tid == 0) atomicAdd(&g_xcnt[j >> 4], 1);   // t complete when ==16
        return;
    }

    // ================= role: scan =================
    if (bid == SCAN_BID) {
        // wait for circuit parameters
        if (tid == 0) { while (vload(&g_parflag) < 4) __nanosleep(64); }
        __syncthreads();

        float ws_f = __ldcg(&g_par[0][0]), A2_f = __ldcg(&g_par[0][2]), R2_f = __ldcg(&g_par[0][3]);
        float ws_i = __ldcg(&g_par[1][0]), A2_i = __ldcg(&g_par[1][2]), R2_i = __ldcg(&g_par[1][3]);
        float ws_g = __ldcg(&g_par[2][0]), A_g  = __ldcg(&g_par[2][4]), R_g  = __ldcg(&g_par[2][5]);
        float ws_o = __ldcg(&g_par[3][0]), A2_o = __ldcg(&g_par[3][2]), R2_o = __ldcg(&g_par[3][3]);
        float off_f = __ldcg(&g_par[0][1]), off_i = __ldcg(&g_par[1][1]);
        float off_g = __ldcg(&g_par[2][1]), off_o = __ldcg(&g_par[3][1]);

        float H = 0.f, C = 0.f;
        int b = tid & 127;   // threads 128-255 only hit barriers

        const float4* Xd = g_xdot;
#define LOADADJ(t) \
    ({ float4 v_ = __ldcg(&Xd[(t) * BATCH + b]); \
       v_.x += off_f; v_.y += off_i; v_.z += off_g; v_.w += off_o; v_; })

        // wait for t=0..7, preload ring
        if (tid == 0) {
            for (int j = 0; j < 8; j++) while (vload(&g_xcnt[j]) < 16) __nanosleep(64);
        }
        __syncthreads();

        float4 q[8];
        if (tid < 128) {
#pragma unroll
            for (int j = 0; j < 8; j++) q[j] = LOADADJ(j);
        }

#define STEP(xd, t)                                                   \
    {                                                                 \
        float cf = __cosf(fmaf(H, ws_f, (xd).x));                     \
        float ci = __cosf(fmaf(H, ws_i, (xd).y));                     \
        float cg = __cosf(fmaf(H, ws_g, (xd).z));                     \
        float co = __cosf(fmaf(H, ws_o, (xd).w));                     \
        float fv = fmaf(htanh(fmaf(R2_f, cf, A2_f)), 0.5f, 0.5f);     \
        float iv = fmaf(htanh(fmaf(R2_i, ci, A2_i)), 0.5f, 0.5f);     \
        float gv = htanh(fmaf(R_g, cg, A_g));                         \
        float ov = fmaf(htanh(fmaf(R2_o, co, A2_o)), 0.5f, 0.5f);     \
        C = fmaf(fv, C, iv * gv);                                     \
        H = ov * htanh(C);                                            \
        g_H[(t) * BATCH + b] = H;                                     \
    }

#pragma unroll 1
        for (int t = 0; t < T_STEPS; t += 8) {
            // ensure next chunk's inputs (t+8..t+15) are ready before prefetching
            if (tid == 0 && t + 8 < T_STEPS) {
                for (int j = t + 8; j < t + 16; j++)
                    while (vload(&g_xcnt[j]) < 16) __nanosleep(64);
            }
            __syncthreads();
            if (tid < 128) {
#pragma unroll
                for (int j = 0; j < 8; j++) {
                    float4 cur = q[j];
                    if (t + 8 + j < T_STEPS) q[j] = LOADADJ(t + 8 + j);
                    STEP(cur, t + j);
                }
            }
            __syncthreads();
            if (tid == 0 && t + 8 < T_STEPS) {
                __threadfence();                         // release H[..t+8)
                *(volatile int*)&g_hprog = t + 8;
            }
        }
#undef STEP
#undef LOADADJ
        if (tid < 128) g_Cfin[b] = C;
        __syncthreads();
        if (tid == 0) {
            __threadfence();                             // release H + Cfin
            *(volatile int*)&g_hprog = T_STEPS;
        }
        return;
    }

    // ================= role: bcast consumer =================
    {
        const unsigned OUT4 = (unsigned)T_STEPS * BATCH * (HID / 4); // 4,194,304
        const unsigned HB4  = (unsigned)BATCH * (HID / 4);           // 16,384
        int k = bid - BCAST0;                 // 0..16511
        int target = (k < 16384) ? (k >> 6) + 1 : T_STEPS;  // t needed: t = k/64

        if (tid == 0) { while (vload(&g_hprog) < target) __nanosleep(256); }
        __syncthreads();

        unsigned i = (unsigned)k * 256u + tid;           // float4 index
        float v;
        if (i < OUT4) {
            v = __ldcg(&g_H[i >> 7]);                                  // row = i/128
        } else if (i < OUT4 + HB4) {
            v = __ldcg(&g_H[(T_STEPS - 1) * BATCH + ((i - OUT4) >> 7)]);  // hx
        } else {
            v = __ldcg(&g_Cfin[(i - OUT4 - HB4) >> 7]);                // cx
        }
        __stcs(out + i, make_float4(v, v, v, v));
    }
}

// ---------------- launch ----------------
extern "C" void kernel_launch(void* const* d_in, const int* in_sizes, int n_in,
                              void* d_out, int out_size)
{
    const float* X  = (const float*)d_in[0];
    const float* Wf = (const float*)d_in[1];
    const float* bf = (const float*)d_in[2];
    const float* Pf = (const float*)d_in[3];
    const float* Wi = (const float*)d_in[4];
    const float* bi = (const float*)d_in[5];
    const float* Pi = (const float*)d_in[6];
    const float* Wg = (const float*)d_in[7];
    const float* bg = (const float*)d_in[8];
    const float* Pg = (const float*)d_in[9];
    const float* Wo = (const float*)d_in[10];
    const float* bo = (const float*)d_in[11];
    const float* Po = (const float*)d_in[12];

    init_kernel<<<1, 256>>>();

    pipe_kernel<<<GRID_BLKS, 256>>>(
        (float4*)d_out, X,
        Wf, Wi, Wg, Wo,
        bf, bi, bg, bo,
        Pf, Pi, Pg, Po);
}

// round 6
// speedup vs baseline: 1.3703x; 1.3703x over previous
#include <cuda_runtime.h>
#include <cuda_bf16.h>

#define T_STEPS 256
#define BATCH   128
#define DIM_IN  512
#define HID     512
#define NQ      8
#define QDIM    256   // 2^8

#define N_TILES   4096     // xdot tiles: 8 rows each, 32768 rows total
#define N_CHUNKS  16512    // bcast chunks: 256 float4 each = 4,227,072 float4
#define SCAN_BID  4

// ---------------- scratch (no allocations allowed) ----------------
__device__ float4 g_xdot[T_STEPS * BATCH];   // per (t,b): raw dots for f,i,g,o
__device__ float  g_H[T_STEPS * BATCH];      // scalar hidden state per (t,b)
__device__ float  g_Cfin[BATCH];             // final cell scalar per b
// per gate: [0]=wsum  [1]=b0-phi  [2]=alpha/2  [3]=R/2  [4]=alpha  [5]=R
__device__ float  g_par[4][6];
// pipeline flags (reset by init_kernel every launch)
__device__ int    g_xcnt[T_STEPS];   // per-t warp completions (target 128)
__device__ int    g_parflag;         // circuits completed (target 4)
__device__ int    g_hprog;           // scan progress: H[0..g_hprog) valid; 256 = all + Cfin

__device__ __forceinline__ float2 cmul(float2 a, float2 b) {
    return make_float2(a.x * b.x - a.y * b.y, a.x * b.y + a.y * b.x);
}
__device__ __forceinline__ float2 cadd(float2 a, float2 b) {
    return make_float2(a.x + b.x, a.y + b.y);
}
__device__ __forceinline__ float htanh(float x) {
    float y;
    asm("tanh.approx.f32 %0, %1;" : "=f"(y) : "f"(x));
    return y;
}
__device__ __forceinline__ int vload(const int* p) {
    return *(volatile const int*)p;
}

// ---------------- init: zero the pipeline flags ----------------
__global__ void init_kernel()
{
    int i = threadIdx.x;
    if (i < T_STEPS) g_xcnt[i] = 0;
    if (i == 0) { g_parflag = 0; g_hprog = 0; }
}

// ---------------- circuit: simulate one variational circuit ----------------
__device__ void circuit_block(int g, const float* __restrict__ P,
                              const float* __restrict__ W, const float* __restrict__ bv)
{
    __shared__ float2 a0[QDIM], a1[QDIM];
    __shared__ float  r0[QDIM], r1[QDIM], r2[QDIM];
    int d = threadIdx.x;

    a0[d] = make_float2(d == 0 ? 1.f : 0.f, 0.f);
    a1[d] = make_float2(d == QDIM / 2 ? 1.f : 0.f, 0.f);

    for (int l = 0; l < 2; l++) {
        for (int w = 0; w < NQ; w++) {
            const float* p = P + (l * NQ + w) * 3;
            float phi = p[0], th = p[1], om = p[2];
            float c, s;  __sincosf(0.5f * th, &s, &c);
            float cap, sap; __sincosf(0.5f * (phi + om), &sap, &cap);
            float cbm, sbm; __sincosf(0.5f * (phi - om), &sbm, &cbm);
            float2 m00 = make_float2(cap * c, -sap * c);     // ep*c
            float2 m01 = make_float2(-cbm * s, -sbm * s);    // -em*s
            float2 m10 = make_float2(cbm * s, -sbm * s);     // conj(em)*s
            float2 m11 = make_float2(cap * c, sap * c);      // conj(ep)*c

            int p7 = 7 - w;
            int mask = 1 << p7;
            int bit = (d >> p7) & 1;
            __syncthreads();
            float2 me0 = a0[d], pa0 = a0[d ^ mask];
            float2 me1 = a1[d], pa1 = a1[d ^ mask];
            __syncthreads();
            float2 n0, n1;
            if (!bit) {
                n0 = cadd(cmul(m00, me0), cmul(m01, pa0));
                n1 = cadd(cmul(m00, me1), cmul(m01, pa1));
            } else {
                n0 = cadd(cmul(m10, pa0), cmul(m11, me0));
                n1 = cadd(cmul(m10, pa1), cmul(m11, me1));
            }
            a0[d] = n0; a1[d] = n1;
        }
        for (int w = 0; w < NQ - 1; w++) {
            int pc = 7 - w, pt = 6 - w;
            __syncthreads();
            int src = ((d >> pc) & 1) ? (d ^ (1 << pt)) : d;
            float2 v0 = a0[src], v1 = a1[src];
            __syncthreads();
            a0[d] = v0; a1[d] = v1;
        }
    }
    __syncthreads();

    float z = (d < QDIM / 2) ? 1.f : -1.f;
    float2 c0 = a0[d], c1 = a1[d];
    r0[d] = z * (c0.x * c0.x + c0.y * c0.y);
    r1[d] = z * (c1.x * c1.x + c1.y * c1.y);
    r2[d] = z * (c0.y * c1.x - c0.x * c1.y);
    __syncthreads();
    for (int off = QDIM / 2; off; off >>= 1) {
        if (d < off) { r0[d] += r0[d + off]; r1[d] += r1[d + off]; r2[d] += r2[d + off]; }
        __syncthreads();
    }
    float S00 = r0[0], S11 = r1[0], S01 = r2[0];
    __syncthreads();

    r0[d] = W[512 + d] + W[512 + QDIM + d];
    __syncthreads();
    for (int off = QDIM / 2; off; off >>= 1) {
        if (d < off) r0[d] += r0[d + off];
        __syncthreads();
    }
    if (d == 0) {
        float alpha = 0.5f * (S00 + S11);
        float beta  = 0.5f * (S00 - S11);
        float gamma = -S01;
        float R   = sqrtf(beta * beta + gamma * gamma);
        float phi = atan2f(gamma, beta);
        g_par[g][0] = r0[0];          // wsum
        g_par[g][1] = bv[0] - phi;    // theta offset (added in scan)
        g_par[g][2] = 0.5f * alpha;
        g_par[g][3] = 0.5f * R;
        g_par[g][4] = alpha;
        g_par[g][5] = R;
        __threadfence();              // release g_par
        atomicAdd(&g_parflag, 1);
    }
    __syncthreads();
}

// ---------------- persistent fused pipeline kernel ----------------
// Grid is sized so EVERY block is resident in wave 1 (occupancy-derived).
// blocks 0-3: circuit, then join worker pool. block 4: scan.
// all other blocks: workers (xdot tiles in t-order, then bcast chunks).
__global__ void __launch_bounds__(256, 3) pipe_kernel(
    float4* __restrict__ out,
    const float* __restrict__ X,
    const float* __restrict__ Wf, const float* __restrict__ Wi,
    const float* __restrict__ Wg, const float* __restrict__ Wo,
    const float* __restrict__ bfv, const float* __restrict__ biv,
    const float* __restrict__ bgv, const float* __restrict__ bov,
    const float* __restrict__ Pf, const float* __restrict__ Pi,
    const float* __restrict__ Pg, const float* __restrict__ Po)
{
    int bid = blockIdx.x;
    int tid = threadIdx.x;

    // ================= role: scan =================
    if (bid == SCAN_BID) {
        if (tid == 0) { while (vload(&g_parflag) < 4) __nanosleep(64); }
        __syncthreads();

        float ws_f = __ldcg(&g_par[0][0]), A2_f = __ldcg(&g_par[0][2]), R2_f = __ldcg(&g_par[0][3]);
        float ws_i = __ldcg(&g_par[1][0]), A2_i = __ldcg(&g_par[1][2]), R2_i = __ldcg(&g_par[1][3]);
        float ws_g = __ldcg(&g_par[2][0]), A_g  = __ldcg(&g_par[2][4]), R_g  = __ldcg(&g_par[2][5]);
        float ws_o = __ldcg(&g_par[3][0]), A2_o = __ldcg(&g_par[3][2]), R2_o = __ldcg(&g_par[3][3]);
        float off_f = __ldcg(&g_par[0][1]), off_i = __ldcg(&g_par[1][1]);
        float off_g = __ldcg(&g_par[2][1]), off_o = __ldcg(&g_par[3][1]);

        float H = 0.f, C = 0.f;
        int b = tid & 127;   // threads 128-255 only participate in barriers

        const float4* Xd = g_xdot;
#define LOADADJ(t) \
    ({ float4 v_ = __ldcg(&Xd[(t) * BATCH + b]); \
       v_.x += off_f; v_.y += off_i; v_.z += off_g; v_.w += off_o; v_; })

        if (tid == 0) {
            for (int j = 0; j < 8; j++) while (vload(&g_xcnt[j]) < 128) __nanosleep(64);
        }
        __syncthreads();

        float4 q[8];
        if (tid < 128) {
#pragma unroll
            for (int j = 0; j < 8; j++) q[j] = LOADADJ(j);
        }

#define STEP(xd, t)                                                   \
    {                                                                 \
        float cf = __cosf(fmaf(H, ws_f, (xd).x));                     \
        float ci = __cosf(fmaf(H, ws_i, (xd).y));                     \
        float cg = __cosf(fmaf(H, ws_g, (xd).z));                     \
        float co = __cosf(fmaf(H, ws_o, (xd).w));                     \
        float fv = fmaf(htanh(fmaf(R2_f, cf, A2_f)), 0.5f, 0.5f);     \
        float iv = fmaf(htanh(fmaf(R2_i, ci, A2_i)), 0.5f, 0.5f);     \
        float gv = htanh(fmaf(R_g, cg, A_g));                         \
        float ov = fmaf(htanh(fmaf(R2_o, co, A2_o)), 0.5f, 0.5f);     \
        C = fmaf(fv, C, iv * gv);                                     \
        H = ov * htanh(C);                                            \
        g_H[(t) * BATCH + b] = H;                                     \
    }

#pragma unroll 1
        for (int t = 0; t < T_STEPS; t += 8) {
            if (tid == 0 && t + 8 < T_STEPS) {
                for (int j = t + 8; j < t + 16; j++)
                    while (vload(&g_xcnt[j]) < 128) __nanosleep(64);
            }
            __syncthreads();
            if (tid < 128) {
#pragma unroll
                for (int j = 0; j < 8; j++) {
                    float4 cur = q[j];
                    if (t + 8 + j < T_STEPS) q[j] = LOADADJ(t + 8 + j);
                    STEP(cur, t + j);
                }
                __threadfence();                 // release this thread's H stores
            }
            __syncthreads();
            if (tid == 0 && t + 8 < T_STEPS)
                *(volatile int*)&g_hprog = t + 8;
        }
#undef STEP
#undef LOADADJ
        if (tid < 128) {
            g_Cfin[b] = C;
            __threadfence();
        }
        __syncthreads();
        if (tid == 0) *(volatile int*)&g_hprog = T_STEPS;
        return;
    }

    // ================= role: circuit (then fall through to worker) =================
    if (bid < 4) {
        int g = bid;
        const float* P  = (g == 0) ? Pf : (g == 1) ? Pi : (g == 2) ? Pg : Po;
        const float* W  = (g == 0) ? Wf : (g == 1) ? Wi : (g == 2) ? Wg : Wo;
        const float* bv = (g == 0) ? bfv : (g == 1) ? biv : (g == 2) ? bgv : bov;
        circuit_block(g, P, W, bv);
    }

    // ================= role: worker (xdot tiles, then bcast chunks) =================
    {
        int wid  = (bid < 4) ? bid : bid - 1;   // skip scan block
        int NW   = gridDim.x - 1;
        int warp = tid >> 5;
        int lane = tid & 31;

        const float4* wf = (const float4*)Wf;
        const float4* wi = (const float4*)Wi;
        const float4* wg = (const float4*)Wg;
        const float4* wo = (const float4*)Wo;

        // ---- xdot: tiles interleaved so low t completes first grid-wide ----
        for (int tile = wid; tile < N_TILES; tile += NW) {
            int row = tile * 8 + warp;
            const float4* xr = (const float4*)(X + (size_t)row * DIM_IN);

            // front-batch the 4 X loads (MLP), weights from L1/L2
            float4 x0 = xr[lane], x1 = xr[lane + 32], x2 = xr[lane + 64], x3 = xr[lane + 96];

            float sf, si, sg, so;
            {
                float4 a0 = __ldg(wf + lane), a1 = __ldg(wf + lane + 32),
                       a2 = __ldg(wf + lane + 64), a3 = __ldg(wf + lane + 96);
                sf = x0.x*a0.x + x0.y*a0.y + x0.z*a0.z + x0.w*a0.w
                   + x1.x*a1.x + x1.y*a1.y + x1.z*a1.z + x1.w*a1.w
                   + x2.x*a2.x + x2.y*a2.y + x2.z*a2.z + x2.w*a2.w
                   + x3.x*a3.x + x3.y*a3.y + x3.z*a3.z + x3.w*a3.w;
            }
            {
                float4 a0 = __ldg(wi + lane), a1 = __ldg(wi + lane + 32),
                       a2 = __ldg(wi + lane + 64), a3 = __ldg(wi + lane + 96);
                si = x0.x*a0.x + x0.y*a0.y + x0.z*a0.z + x0.w*a0.w
                   + x1.x*a1.x + x1.y*a1.y + x1.z*a1.z + x1.w*a1.w
                   + x2.x*a2.x + x2.y*a2.y + x2.z*a2.z + x2.w*a2.w
                   + x3.x*a3.x + x3.y*a3.y + x3.z*a3.z + x3.w*a3.w;
            }
            {
                float4 a0 = __ldg(wg + lane), a1 = __ldg(wg + lane + 32),
                       a2 = __ldg(wg + lane + 64), a3 = __ldg(wg + lane + 96);
                sg = x0.x*a0.x + x0.y*a0.y + x0.z*a0.z + x0.w*a0.w
                   + x1.x*a1.x + x1.y*a1.y + x1.z*a1.z + x1.w*a1.w
                   + x2.x*a2.x + x2.y*a2.y + x2.z*a2.z + x2.w*a2.w
                   + x3.x*a3.x + x3.y*a3.y + x3.z*a3.z + x3.w*a3.w;
            }
            {
                float4 a0 = __ldg(wo + lane), a1 = __ldg(wo + lane + 32),
                       a2 = __ldg(wo + lane + 64), a3 = __ldg(wo + lane + 96);
                so = x0.x*a0.x + x0.y*a0.y + x0.z*a0.z + x0.w*a0.w
                   + x1.x*a1.x + x1.y*a1.y + x1.z*a1.z + x1.w*a1.w
                   + x2.x*a2.x + x2.y*a2.y + x2.z*a2.z + x2.w*a2.w
                   + x3.x*a3.x + x3.y*a3.y + x3.z*a3.z + x3.w*a3.w;
            }
#pragma unroll
            for (int o = 16; o; o >>= 1) {
                sf += __shfl_xor_sync(0xffffffffu, sf, o);
                si += __shfl_xor_sync(0xffffffffu, si, o);
                sg += __shfl_xor_sync(0xffffffffu, sg, o);
                so += __shfl_xor_sync(0xffffffffu, so, o);
            }
            if (lane == 0) {
                g_xdot[row] = make_float4(sf, si, sg, so);
                __threadfence();                       // release row
                atomicAdd(&g_xcnt[tile >> 4], 1);      // t complete at 128
            }
        }

        // ---- bcast: chunks interleaved, gated on scan progress ----
        const unsigned OUT4 = (unsigned)T_STEPS * BATCH * (HID / 4); // 4,194,304
        const unsigned HB4  = (unsigned)BATCH * (HID / 4);           // 16,384
        for (int c = wid; c < N_CHUNKS; c += NW) {
            int target = (c < 16384) ? (c >> 6) + 1 : T_STEPS;
            if (tid == 0) { while (vload(&g_hprog) < target) __nanosleep(128); }
            __syncthreads();

            unsigned i = (unsigned)c * 256u + tid;     // float4 index
            float v;
            if (i < OUT4) {
                v = __ldcg(&g_H[i >> 7]);
            } else if (i < OUT4 + HB4) {
                v = __ldcg(&g_H[(T_STEPS - 1) * BATCH + ((i - OUT4) >> 7)]);
            } else {
                v = __ldcg(&g_Cfin[(i - OUT4 - HB4) >> 7]);
            }
            __stcs(out + i, make_float4(v, v, v, v));
        }
    }
}

// ---------------- launch ----------------
extern "C" void kernel_launch(void* const* d_in, const int* in_sizes, int n_in,
                              void* d_out, int out_size)
{
    const float* X  = (const float*)d_in[0];
    const float* Wf = (const float*)d_in[1];
    const float* bf = (const float*)d_in[2];
    const float* Pf = (const float*)d_in[3];
    const float* Wi = (const float*)d_in[4];
    const float* bi = (const float*)d_in[5];
    const float* Pi = (const float*)d_in[6];
    const float* Wg = (const float*)d_in[7];
    const float* bg = (const float*)d_in[8];
    const float* Pg = (const float*)d_in[9];
    const float* Wo = (const float*)d_in[10];
    const float* bo = (const float*)d_in[11];
    const float* Po = (const float*)d_in[12];

    // size the grid so every block is resident in wave 1 (no scheduling deadlock)
    int sms = 0, maxb = 0;
    cudaDeviceGetAttribute(&sms, cudaDevAttrMultiProcessorCount, 0);
    cudaOccupancyMaxActiveBlocksPerMultiprocessor(&maxb, pipe_kernel, 256, 0);
    if (maxb < 1) maxb = 1;
    if (maxb > 8) maxb = 8;
    int grid = sms * maxb;
    if (grid < 8) grid = 8;   // must cover roles 0..4 plus workers

    init_kernel<<<1, 256>>>();

    pipe_kernel<<<grid, 256>>>(
        (float4*)d_out, X,
        Wf, Wi, Wg, Wo,
        bf, bi, bg, bo,
        Pf, Pi, Pg, Po);
}

// round 8
// speedup vs baseline: 2.5758x; 1.8797x over previous
#include <cuda_runtime.h>
#include <cuda_bf16.h>

#define T_STEPS 256
#define BATCH   128
#define DIM_IN  512
#define HID     512
#define NQ      8
#define QDIM    256   // 2^8

// ---------------- scratch (no allocations allowed) ----------------
__device__ float4 g_xdot[T_STEPS * BATCH];   // per (t,b): raw dots for f,i,g,o
__device__ float  g_H[T_STEPS * BATCH];      // scalar hidden state per (t,b)
__device__ float  g_Cfin[BATCH];             // final cell scalar per b
// per gate: [0]=wsum  [1]=b0-phi  [2]=alpha/2  [3]=R/2  [4]=alpha  [5]=R
__device__ float  g_par[4][6];

__device__ __forceinline__ float2 cmul(float2 a, float2 b) {
    return make_float2(a.x * b.x - a.y * b.y, a.x * b.y + a.y * b.x);
}
__device__ __forceinline__ float2 cadd(float2 a, float2 b) {
    return make_float2(a.x + b.x, a.y + b.y);
}
__device__ __forceinline__ float htanh(float x) {
    float y;
    asm("tanh.approx.f32 %0, %1;" : "=f"(y) : "f"(x));
    return y;
}
__device__ __forceinline__ float dot4(float4 w, float4 x) {
    return w.x * x.x + w.y * x.y + w.z * x.z + w.w * x.w;
}

// ---------------- circuit: simulate one variational circuit ----------------
// Statevector-simulates columns 0 and 128 of the 2-layer circuit, reduces to
// expval(theta) = alpha + R*cos(theta - phi), plus wsum and b0-phi.
__device__ void circuit_block(int g, const float* __restrict__ P,
                              const float* __restrict__ W, const float* __restrict__ bv)
{
    __shared__ float2 a0[QDIM], a1[QDIM];
    __shared__ float  r0[QDIM], r1[QDIM], r2[QDIM];
    int d = threadIdx.x;

    a0[d] = make_float2(d == 0 ? 1.f : 0.f, 0.f);
    a1[d] = make_float2(d == QDIM / 2 ? 1.f : 0.f, 0.f);

    for (int l = 0; l < 2; l++) {
        for (int w = 0; w < NQ; w++) {
            const float* p = P + (l * NQ + w) * 3;
            float phi = p[0], th = p[1], om = p[2];
            float c, s;  __sincosf(0.5f * th, &s, &c);
            float cap, sap; __sincosf(0.5f * (phi + om), &sap, &cap);
            float cbm, sbm; __sincosf(0.5f * (phi - om), &sbm, &cbm);
            float2 m00 = make_float2(cap * c, -sap * c);     // ep*c
            float2 m01 = make_float2(-cbm * s, -sbm * s);    // -em*s
            float2 m10 = make_float2(cbm * s, -sbm * s);     // conj(em)*s
            float2 m11 = make_float2(cap * c, sap * c);      // conj(ep)*c

            int p7 = 7 - w;
            int mask = 1 << p7;
            int bit = (d >> p7) & 1;
            __syncthreads();
            float2 me0 = a0[d], pa0 = a0[d ^ mask];
            float2 me1 = a1[d], pa1 = a1[d ^ mask];
            __syncthreads();
            float2 n0, n1;
            if (!bit) {
                n0 = cadd(cmul(m00, me0), cmul(m01, pa0));
                n1 = cadd(cmul(m00, me1), cmul(m01, pa1));
            } else {
                n0 = cadd(cmul(m10, pa0), cmul(m11, me0));
                n1 = cadd(cmul(m10, pa1), cmul(m11, me1));
            }
            a0[d] = n0; a1[d] = n1;
        }
        for (int w = 0; w < NQ - 1; w++) {
            int pc = 7 - w, pt = 6 - w;
            __syncthreads();
            int src = ((d >> pc) & 1) ? (d ^ (1 << pt)) : d;
            float2 v0 = a0[src], v1 = a1[src];
            __syncthreads();
            a0[d] = v0; a1[d] = v1;
        }
    }
    __syncthreads();

    float z = (d < QDIM / 2) ? 1.f : -1.f;
    float2 c0 = a0[d], c1 = a1[d];
    r0[d] = z * (c0.x * c0.x + c0.y * c0.y);
    r1[d] = z * (c1.x * c1.x + c1.y * c1.y);
    r2[d] = z * (c0.y * c1.x - c0.x * c1.y);
    __syncthreads();
    for (int off = QDIM / 2; off; off >>= 1) {
        if (d < off) { r0[d] += r0[d + off]; r1[d] += r1[d + off]; r2[d] += r2[d + off]; }
        __syncthreads();
    }
    float S00 = r0[0], S11 = r1[0], S01 = r2[0];
    __syncthreads();

    r0[d] = W[512 + d] + W[512 + QDIM + d];
    __syncthreads();
    for (int off = QDIM / 2; off; off >>= 1) {
        if (d < off) r0[d] += r0[d + off];
        __syncthreads();
    }
    if (d == 0) {
        float alpha = 0.5f * (S00 + S11);
        float beta  = 0.5f * (S00 - S11);
        float gamma = -S01;
        float R   = sqrtf(beta * beta + gamma * gamma);
        float phi = atan2f(gamma, beta);
        g_par[g][0] = r0[0];          // wsum
        g_par[g][1] = bv[0] - phi;    // theta offset (added in scan)
        g_par[g][2] = 0.5f * alpha;
        g_par[g][3] = 0.5f * R;
        g_par[g][4] = alpha;
        g_par[g][5] = R;
    }
}

// ---------------- prep: circuit (blocks 0-3) + xdot, 2 rows per warp ----------------
// 2 rows/warp halves the L1 weight re-read per row (was the L1 bottleneck) and
// doubles the front-batched DRAM loads in flight per thread.
__global__ void __launch_bounds__(256, 4) prep_kernel(
    const float* __restrict__ X,
    const float* __restrict__ Wf, const float* __restrict__ Wi,
    const float* __restrict__ Wg, const float* __restrict__ Wo,
    const float* __restrict__ bfv, const float* __restrict__ biv,
    const float* __restrict__ bgv, const float* __restrict__ bov,
    const float* __restrict__ Pf, const float* __restrict__ Pi,
    const float* __restrict__ Pg, const float* __restrict__ Po)
{
    if (blockIdx.x < 4) {
        int g = blockIdx.x;
        const float* P  = (g == 0) ? Pf : (g == 1) ? Pi : (g == 2) ? Pg : Po;
        const float* W  = (g == 0) ? Wf : (g == 1) ? Wi : (g == 2) ? Wg : Wo;
        const float* bv = (g == 0) ? bfv : (g == 1) ? biv : (g == 2) ? bgv : bov;
        circuit_block(g, P, W, bv);
        return;
    }

    int j    = blockIdx.x - 4;           // 0..2047 ; 16 rows per block
    int warp = threadIdx.x >> 5;
    int lane = threadIdx.x & 31;
    int rA   = j * 16 + warp * 2;        // rows rA, rA+1

    const float4* xa = (const float4*)(X + (size_t)rA * DIM_IN);
    const float4* xb = xa + (DIM_IN / 4);

    // front-batch all 8 X loads (MLP=8)
    float4 A0 = xa[lane], A1 = xa[lane + 32], A2 = xa[lane + 64], A3 = xa[lane + 96];
    float4 B0 = xb[lane], B1 = xb[lane + 32], B2 = xb[lane + 64], B3 = xb[lane + 96];

    float fA, fB, iA, iB, gA, gB, oA, oB;

#define GDOT(Wp, dA, dB)                                                          \
    {                                                                             \
        const float4* w4 = (const float4*)(Wp);                                   \
        float4 w0 = __ldg(w4 + lane),      w1 = __ldg(w4 + lane + 32),            \
               w2 = __ldg(w4 + lane + 64), w3 = __ldg(w4 + lane + 96);            \
        dA = dot4(w0, A0) + dot4(w1, A1) + dot4(w2, A2) + dot4(w3, A3);           \
        dB = dot4(w0, B0) + dot4(w1, B1) + dot4(w2, B2) + dot4(w3, B3);           \
    }
    GDOT(Wf, fA, fB)
    GDOT(Wi, iA, iB)
    GDOT(Wg, gA, gB)
    GDOT(Wo, oA, oB)
#undef GDOT

#pragma unroll
    for (int o = 16; o; o >>= 1) {
        fA += __shfl_xor_sync(0xffffffffu, fA, o);
        fB += __shfl_xor_sync(0xffffffffu, fB, o);
        iA += __shfl_xor_sync(0xffffffffu, iA, o);
        iB += __shfl_xor_sync(0xffffffffu, iB, o);
        gA += __shfl_xor_sync(0xffffffffu, gA, o);
        gB += __shfl_xor_sync(0xffffffffu, gB, o);
        oA += __shfl_xor_sync(0xffffffffu, oA, o);
        oB += __shfl_xor_sync(0xffffffffu, oB, o);
    }
    if (lane == 0) {
        g_xdot[rA]     = make_float4(fA, iA, gA, oA);
        g_xdot[rA + 1] = make_float4(fB, iB, gB, oB);
    }
}

// ---------------- scan: 128 scalar recurrences, 256 steps ----------------
// theta_g = (xd_g + off_g) + H*ws_g ; gate = act(alpha_g + R_g*cos(theta_g)).
// The three sigmoids have tanh-args in [-0.5,0.5] (expval in [-1,1]), so they
// use a 7th-order odd Taylor poly on the FMA pipe; gv and tanh(C) (wider args)
// stay on HW tanh. This drops the MUFU issue floor from 9 to 6 ops/step.
__device__ __forceinline__ float ptanh_half(float x) {   // |x| <= ~0.55
    float t = x * x;
    float p = fmaf(t, -17.f / 315.f, 2.f / 15.f);
    p = fmaf(t, p, -1.f / 3.f);
    p = fmaf(t, p, 1.f);
    return x * p;
}

__global__ void scan_kernel()
{
    int b = threadIdx.x;

    float ws_f = g_par[0][0], A2_f = g_par[0][2], R2_f = g_par[0][3];
    float ws_i = g_par[1][0], A2_i = g_par[1][2], R2_i = g_par[1][3];
    float ws_g = g_par[2][0], A_g  = g_par[2][4], R_g  = g_par[2][5];
    float ws_o = g_par[3][0], A2_o = g_par[3][2], R2_o = g_par[3][3];
    float off_f = g_par[0][1], off_i = g_par[1][1], off_g = g_par[2][1], off_o = g_par[3][1];

    float H = 0.f, C = 0.f;

    const float4* X = g_xdot;
#define LOADADJ(t) \
    ({ float4 v_ = X[(t) * BATCH + b]; \
       v_.x += off_f; v_.y += off_i; v_.z += off_g; v_.w += off_o; v_; })

    float4 q[8];
#pragma unroll
    for (int j = 0; j < 8; j++) q[j] = LOADADJ(j);

#define STEP(xd, t)                                                   \
    {                                                                 \
        float cf = __cosf(fmaf(H, ws_f, (xd).x));                     \
        float ci = __cosf(fmaf(H, ws_i, (xd).y));                     \
        float cg = __cosf(fmaf(H, ws_g, (xd).z));                     \
        float co = __cosf(fmaf(H, ws_o, (xd).w));                     \
        float fv = fmaf(ptanh_half(fmaf(R2_f, cf, A2_f)), 0.5f, 0.5f);\
        float iv = fmaf(ptanh_half(fmaf(R2_i, ci, A2_i)), 0.5f, 0.5f);\
        float gv = htanh(fmaf(R_g, cg, A_g));                         \
        float ov = fmaf(ptanh_half(fmaf(R2_o, co, A2_o)), 0.5f, 0.5f);\
        C = fmaf(fv, C, iv * gv);                                     \
        H = ov * htanh(C);                                            \
        g_H[(t) * BATCH + b] = H;                                     \
    }

#pragma unroll 1
    for (int t = 0; t < T_STEPS; t += 8) {
#pragma unroll
        for (int j = 0; j < 8; j++) {
            float4 cur = q[j];
            if (t + 8 + j < T_STEPS) q[j] = LOADADJ(t + 8 + j);
            STEP(cur, t + j);
        }
    }
#undef STEP
#undef LOADADJ
    g_Cfin[b] = C;
}

// ---------------- bcast: broadcast scalars into the full output ----------------
// 1 float4 per thread, perfectly coalesced; streaming stores (write-once data).
// d_out layout: outputs (T,B,512) ++ hx (B,512) ++ cx (B,512).
__global__ void bcast_kernel(float4* __restrict__ out)
{
    const unsigned OUT4 = (unsigned)T_STEPS * BATCH * (HID / 4); // 4,194,304
    const unsigned HB4  = (unsigned)BATCH * (HID / 4);           // 16,384
    unsigned i = blockIdx.x * blockDim.x + threadIdx.x;          // float4 index
    float v;
    if (i < OUT4) {
        v = g_H[i >> 7];                                         // (t*B+b) = i/128
    } else if (i < OUT4 + HB4) {
        v = g_H[(T_STEPS - 1) * BATCH + ((i - OUT4) >> 7)];      // hx
    } else if (i < OUT4 + 2 * HB4) {
        v = g_Cfin[(i - OUT4 - HB4) >> 7];                       // cx
    } else {
        return;
    }
    __stcs(out + i, make_float4(v, v, v, v));
}

// ---------------- launch ----------------
extern "C" void kernel_launch(void* const* d_in, const int* in_sizes, int n_in,
                              void* d_out, int out_size)
{
    const float* X  = (const float*)d_in[0];
    const float* Wf = (const float*)d_in[1];
    const float* bf = (const float*)d_in[2];
    const float* Pf = (const float*)d_in[3];
    const float* Wi = (const float*)d_in[4];
    const float* bi = (const float*)d_in[5];
    const float* Pi = (const float*)d_in[6];
    const float* Wg = (const float*)d_in[7];
    const float* bg = (const float*)d_in[8];
    const float* Pg = (const float*)d_in[9];
    const float* Wo = (const float*)d_in[10];
    const float* bo = (const float*)d_in[11];
    const float* Po = (const float*)d_in[12];

    // blocks 0-3: circuits; blocks 4..2051: xdot (32768 rows / 16 rows per block)
    prep_kernel<<<4 + (T_STEPS * BATCH) / 16, 256>>>(
        X, Wf, Wi, Wg, Wo, bf, bi, bg, bo, Pf, Pi, Pg, Po);

    scan_kernel<<<1, BATCH>>>();

    // 4,194,304 + 32,768 float4 = 4,227,072 = 16512 * 256
    bcast_kernel<<<16512, 256>>>((float4*)d_out);
}